// round 1
// baseline (speedup 1.0000x reference)
#include <cuda_runtime.h>
#include <math.h>

#define NN 20000
#define NE 320000
#define NR 200
#define DL 16
#define G  64
#define DW 300
#define DH 256
#define HD 128
#define NC 2000
#define BB 4
#define TT 32
#define G3 (3*HD)    // 384
#define BG (BB*G)    // 256
#define H1 1024
#define FEAT (G+DH)  // 320

// ---------------- scratch (static device globals; no allocation) ----------------
__device__ float g_gx[2][BB][TT][G3];      // precomputed input gates, both dirs
__device__ float g_qemb[BB][DH];
__device__ float g_qg[BB][G];
__device__ float g_nf0[NN][BG];            // node features before RGCN  [n][b*64+g]
__device__ float g_sacc[NN][BG];           // scattered pre-basis sums
__device__ float g_nf1[NN][BG];            // node features after RGCN
__device__ int   g_deg[NN];
__device__ int   g_off[NN+1];
__device__ int   g_cur[NN];
__device__ int   g_psrc[NE];
__device__ float g_pw[NE];
__device__ float g_scores[BB][NN];
__device__ unsigned g_bmaxU[BB];
__device__ float g_agg[BB][G];
__device__ float g_den[BB];
__device__ float g_hid[BB][H1];

// ---------------- helpers ----------------
__device__ __forceinline__ unsigned fenc(float f) {
    unsigned u = __float_as_uint(f);
    return (u & 0x80000000u) ? ~u : (u | 0x80000000u);
}
__device__ __forceinline__ float fdec(unsigned e) {
    return (e & 0x80000000u) ? __uint_as_float(e & 0x7FFFFFFFu)
                             : __uint_as_float(~e);
}
__device__ __forceinline__ float sigm(float x) { return 1.f / (1.f + __expf(-x)); }

// ---------------- kernels ----------------
__global__ void k_init() {
    int i = blockIdx.x * blockDim.x + threadIdx.x;
    if (i < NN) g_deg[i] = 0;
    if (i < BB * G) ((float*)g_agg)[i] = 0.f;
    if (i < BB) { g_den[i] = 0.f; g_bmaxU[i] = 0u; }
}

// input gates gx = x @ Wx + bx for both directions. 256 blocks x 384 threads.
__global__ void k_gx(const int* __restrict__ q, const float* __restrict__ embw,
                     const float* __restrict__ WxF, const float* __restrict__ bxF,
                     const float* __restrict__ WxB, const float* __restrict__ bxB) {
    int blk = blockIdx.x;
    int d = blk >> 7;          // 0 fwd, 1 bwd
    int bt = blk & 127;
    int b = bt >> 5, t = bt & 31;
    const float* Wx = d ? WxB : WxF;
    const float* bx = d ? bxB : bxF;
    __shared__ float xs[DW];
    int tok = q[b * TT + t];
    for (int k = threadIdx.x; k < DW; k += blockDim.x) xs[k] = embw[tok * DW + k];
    __syncthreads();
    int j = threadIdx.x;
    float acc = bx[j];
    #pragma unroll 4
    for (int k = 0; k < DW; k++) acc = fmaf(xs[k], Wx[k * G3 + j], acc);
    g_gx[d][b][t][j] = acc;
}

// GRU recurrence. 2 blocks (fwd/bwd) x 384 threads; each thread owns one j-column
// with 4 batch accumulators so Wh is read once per step.
__global__ void k_gru(const int* __restrict__ q,
                      const float* __restrict__ WhF, const float* __restrict__ bhF,
                      const float* __restrict__ WhB, const float* __restrict__ bhB) {
    int d = blockIdx.x;
    const float* Wh = d ? WhB : WhF;
    const float* bh = d ? bhB : bhF;
    __shared__ float hs[BB][HD];
    __shared__ float gh[BB][G3];
    int tid = threadIdx.x;   // 384
    for (int i = tid; i < BB * HD; i += blockDim.x) hs[i >> 7][i & 127] = 0.f;
    __syncthreads();
    int j = tid;
    float bj = bh[j];
    for (int s = 0; s < TT; s++) {
        int t = d ? (TT - 1 - s) : s;
        float a0 = bj, a1 = bj, a2 = bj, a3 = bj;
        #pragma unroll 4
        for (int k = 0; k < HD; k++) {
            float w = Wh[k * G3 + j];
            a0 = fmaf(hs[0][k], w, a0);
            a1 = fmaf(hs[1][k], w, a1);
            a2 = fmaf(hs[2][k], w, a2);
            a3 = fmaf(hs[3][k], w, a3);
        }
        gh[0][j] = a0; gh[1][j] = a1; gh[2][j] = a2; gh[3][j] = a3;
        __syncthreads();
        for (int u = tid; u < BB * HD; u += blockDim.x) {
            int b = u >> 7, i = u & 127;
            const float* gx = &g_gx[d][b][t][0];
            float r = sigm(gx[i] + gh[b][i]);
            float z = sigm(gx[HD + i] + gh[b][HD + i]);
            float n = tanhf(gx[2 * HD + i] + r * gh[b][2 * HD + i]);
            float hn = (1.f - z) * n + z * hs[b][i];
            if (q[b * TT + t] != 0) hs[b][i] = hn;
        }
        __syncthreads();
    }
    for (int u = tid; u < BB * HD; u += blockDim.x) {
        int b = u >> 7, i = u & 127;
        g_qemb[b][d * HD + i] = hs[b][i];
    }
}

// q_g = q_emb @ W_hg + b_hg. 1 block x 256.
__global__ void k_qg(const float* __restrict__ Whg, const float* __restrict__ bhg) {
    int tid = threadIdx.x;
    int b = tid >> 6, g = tid & 63;
    float acc = bhg[g];
    #pragma unroll 8
    for (int k = 0; k < DH; k++) acc = fmaf(g_qemb[b][k], Whg[k * G + g], acc);
    g_qg[b][g] = acc;
}

// desc attention -> nf0.  one warp per node; lane owns g-pair (2*lane, 2*lane+1)
__global__ void k_nf0(const int* __restrict__ descs, const float* __restrict__ embd) {
    int warp = (blockIdx.x * blockDim.x + threadIdx.x) >> 5;
    int lane = threadIdx.x & 31;
    if (warp >= NN) return;
    const int n = warp;
    float qg0[BB], qg1[BB];
    #pragma unroll
    for (int b = 0; b < BB; b++) { qg0[b] = g_qg[b][2 * lane]; qg1[b] = g_qg[b][2 * lane + 1]; }
    float dv0[DL], dv1[DL];
    float sc[BB][DL];
    #pragma unroll
    for (int t = 0; t < DL; t++) {
        int tok = descs[n * DL + t];
        float2 e = *(const float2*)&embd[tok * G + 2 * lane];
        dv0[t] = e.x; dv1[t] = e.y;
        #pragma unroll
        for (int b = 0; b < BB; b++) {
            float p = e.x * qg0[b] + e.y * qg1[b];
            p += __shfl_xor_sync(0xFFFFFFFFu, p, 16);
            p += __shfl_xor_sync(0xFFFFFFFFu, p, 8);
            p += __shfl_xor_sync(0xFFFFFFFFu, p, 4);
            p += __shfl_xor_sync(0xFFFFFFFFu, p, 2);
            p += __shfl_xor_sync(0xFFFFFFFFu, p, 1);
            sc[b][t] = p;
        }
    }
    #pragma unroll
    for (int b = 0; b < BB; b++) {
        float m = sc[b][0];
        #pragma unroll
        for (int t = 1; t < DL; t++) m = fmaxf(m, sc[b][t]);
        float den = 0.f, o0 = 0.f, o1 = 0.f;
        #pragma unroll
        for (int t = 0; t < DL; t++) {
            float w = __expf(sc[b][t] - m);
            den += w;
            o0 = fmaf(w, dv0[t], o0);
            o1 = fmaf(w, dv1[t], o1);
        }
        float inv = 1.f / den;
        g_nf0[n][b * G + 2 * lane]     = o0 * inv;
        g_nf0[n][b * G + 2 * lane + 1] = o1 * inv;
    }
}

__global__ void k_deg(const int* __restrict__ dst) {
    int e = blockIdx.x * blockDim.x + threadIdx.x;
    if (e < NE) atomicAdd(&g_deg[dst[e]], 1);
}

// exclusive scan over degrees, single block of 1024
__global__ void k_scan() {
    __shared__ int sm[1024];
    __shared__ int carry;
    int tid = threadIdx.x;
    if (tid == 0) carry = 0;
    __syncthreads();
    for (int base = 0; base < NN; base += 1024) {
        int idx = base + tid;
        int v = (idx < NN) ? g_deg[idx] : 0;
        int x = v;
        for (int ofs = 1; ofs < 1024; ofs <<= 1) {
            sm[tid] = x; __syncthreads();
            if (tid >= ofs) x += sm[tid - ofs];
            __syncthreads();
        }
        if (idx < NN) { int ex = carry + x - v; g_off[idx] = ex; g_cur[idx] = ex; }
        __syncthreads();
        if (tid == 1023) carry += x;
        __syncthreads();
    }
    if (tid == 0) g_off[NN] = carry;
}

__global__ void k_perm(const int* __restrict__ src, const int* __restrict__ dst,
                       const int* __restrict__ et, const float* __restrict__ wcomp) {
    int e = blockIdx.x * blockDim.x + threadIdx.x;
    if (e >= NE) return;
    int pos = atomicAdd(&g_cur[dst[e]], 1);
    g_psrc[pos] = src[e];
    g_pw[pos]   = wcomp[et[e]];
}

// edge aggregation: one warp per dst node; lane owns 8 consecutive floats of the
// 256-float (4 batch x 64) payload. Pure reads + one plain store -> no atomics.
__global__ void k_agg() {
    int warp = (blockIdx.x * blockDim.x + threadIdx.x) >> 5;
    int lane = threadIdx.x & 31;
    if (warp >= NN) return;
    int n = warp;
    int beg = g_off[n], end = g_off[n + 1];
    float4 a0 = {0, 0, 0, 0}, a1 = {0, 0, 0, 0};
    for (int i = beg; i < end; i++) {
        int s = g_psrc[i];
        float w = g_pw[i];
        const float4* hp = (const float4*)&g_nf0[s][lane * 8];
        float4 v0 = hp[0], v1 = hp[1];
        a0.x = fmaf(w, v0.x, a0.x); a0.y = fmaf(w, v0.y, a0.y);
        a0.z = fmaf(w, v0.z, a0.z); a0.w = fmaf(w, v0.w, a0.w);
        a1.x = fmaf(w, v1.x, a1.x); a1.y = fmaf(w, v1.y, a1.y);
        a1.z = fmaf(w, v1.z, a1.z); a1.w = fmaf(w, v1.w, a1.w);
    }
    float4* op = (float4*)&g_sacc[n][lane * 8];
    op[0] = a0; op[1] = a1;
}

// nf1 = relu(s @ bases + bias), fused per-node pooling scores
__global__ void k_rgcn(const float* __restrict__ bases, const float* __restrict__ bias) {
    __shared__ float bs[G * G];
    __shared__ float srow[BG];
    __shared__ float swred[8];
    int tid = threadIdx.x;   // 256
    for (int i = tid; i < G * G; i += 256) bs[i] = bases[i];
    int b = tid >> 6, g = tid & 63;
    float bia = bias[g];
    float qv = g_qg[b][g];
    __syncthreads();
    for (int n = blockIdx.x; n < NN; n += gridDim.x) {
        srow[tid] = g_sacc[n][tid];
        __syncthreads();
        float acc = bia;
        const float* sb = &srow[b * G];
        #pragma unroll 8
        for (int k = 0; k < G; k++) acc = fmaf(sb[k], bs[k * G + g], acc);
        acc = fmaxf(acc, 0.f);
        g_nf1[n][tid] = acc;
        float p = acc * qv;
        p += __shfl_xor_sync(0xFFFFFFFFu, p, 16);
        p += __shfl_xor_sync(0xFFFFFFFFu, p, 8);
        p += __shfl_xor_sync(0xFFFFFFFFu, p, 4);
        p += __shfl_xor_sync(0xFFFFFFFFu, p, 2);
        p += __shfl_xor_sync(0xFFFFFFFFu, p, 1);
        if ((tid & 31) == 0) swred[tid >> 5] = p;
        __syncthreads();
        if (tid < BB) g_scores[tid][n] = swred[2 * tid] + swred[2 * tid + 1];
        __syncthreads();
    }
}

__global__ void k_max() {
    __shared__ unsigned sm[BB][256];
    int tid = threadIdx.x;
    unsigned m[BB] = {0u, 0u, 0u, 0u};
    for (int n = blockIdx.x * blockDim.x + tid; n < NN; n += gridDim.x * blockDim.x) {
        #pragma unroll
        for (int b = 0; b < BB; b++) {
            unsigned e = fenc(g_scores[b][n]);
            m[b] = e > m[b] ? e : m[b];
        }
    }
    #pragma unroll
    for (int b = 0; b < BB; b++) sm[b][tid] = m[b];
    __syncthreads();
    for (int s = 128; s; s >>= 1) {
        if (tid < s) {
            #pragma unroll
            for (int b = 0; b < BB; b++) {
                unsigned o = sm[b][tid + s];
                if (o > sm[b][tid]) sm[b][tid] = o;
            }
        }
        __syncthreads();
    }
    if (tid == 0) {
        #pragma unroll
        for (int b = 0; b < BB; b++) atomicMax(&g_bmaxU[b], sm[b][0]);
    }
}

__global__ void k_sum() {
    int tid = threadIdx.x;   // 256: (b,g)
    int b = tid >> 6, g = tid & 63;
    float m = fdec(g_bmaxU[b]);
    float acc = 0.f, den = 0.f;
    for (int n = blockIdx.x; n < NN; n += gridDim.x) {
        float e = __expf(g_scores[b][n] - m);
        acc = fmaf(e, g_nf1[n][tid], acc);
        if (g == 0) den += e;
    }
    atomicAdd(&g_agg[b][g], acc);
    if (g == 0) atomicAdd(&g_den[b], den);
}

__global__ void k_hidden(const float* __restrict__ W1, const float* __restrict__ b1) {
    int tid = threadIdx.x;   // 1024
    __shared__ float feat[BB][FEAT];
    if (tid < BB * G) { int b = tid >> 6, g = tid & 63; feat[b][g] = g_agg[b][g] / g_den[b]; }
    { int b = tid >> 8, k = tid & 255; feat[b][G + k] = g_qemb[b][k]; }
    __syncthreads();
    float a0 = b1[tid], a1 = a0, a2 = a0, a3 = a0;
    #pragma unroll 4
    for (int k = 0; k < FEAT; k++) {
        float w = W1[k * H1 + tid];
        a0 = fmaf(feat[0][k], w, a0);
        a1 = fmaf(feat[1][k], w, a1);
        a2 = fmaf(feat[2][k], w, a2);
        a3 = fmaf(feat[3][k], w, a3);
    }
    g_hid[0][tid] = fmaxf(a0, 0.f);
    g_hid[1][tid] = fmaxf(a1, 0.f);
    g_hid[2][tid] = fmaxf(a2, 0.f);
    g_hid[3][tid] = fmaxf(a3, 0.f);
}

__global__ void k_logits(const float* __restrict__ W2, const float* __restrict__ b2,
                         float* __restrict__ out) {
    __shared__ float hs[BB][H1];
    for (int i = threadIdx.x; i < BB * H1; i += blockDim.x)
        ((float*)hs)[i] = ((const float*)g_hid)[i];
    __syncthreads();
    int c = blockIdx.x * blockDim.x + threadIdx.x;
    if (c >= NC) return;
    float a0 = b2[c], a1 = a0, a2 = a0, a3 = a0;
    #pragma unroll 4
    for (int k = 0; k < H1; k++) {
        float w = W2[k * NC + c];
        a0 = fmaf(hs[0][k], w, a0);
        a1 = fmaf(hs[1][k], w, a1);
        a2 = fmaf(hs[2][k], w, a2);
        a3 = fmaf(hs[3][k], w, a3);
    }
    out[c] = a0; out[NC + c] = a1; out[2 * NC + c] = a2; out[3 * NC + c] = a3;
}

// ---------------- launch ----------------
extern "C" void kernel_launch(void* const* d_in, const int* in_sizes, int n_in,
                              void* d_out, int out_size) {
    const int*   questions = (const int*)d_in[0];
    const int*   node_descs= (const int*)d_in[1];
    const int*   edge_src  = (const int*)d_in[2];
    const int*   edge_dst  = (const int*)d_in[3];
    const int*   edge_type = (const int*)d_in[4];
    const float* emb_word  = (const float*)d_in[5];
    const float* emb_desc  = (const float*)d_in[6];
    const float* Wx_f = (const float*)d_in[7];
    const float* Wh_f = (const float*)d_in[8];
    const float* bx_f = (const float*)d_in[9];
    const float* bh_f = (const float*)d_in[10];
    const float* Wx_b = (const float*)d_in[11];
    const float* Wh_b = (const float*)d_in[12];
    const float* bx_b = (const float*)d_in[13];
    const float* bh_b = (const float*)d_in[14];
    const float* W_hg = (const float*)d_in[15];
    const float* b_hg = (const float*)d_in[16];
    const float* bases = (const float*)d_in[17];
    const float* w_comp = (const float*)d_in[18];
    const float* rgcn_bias = (const float*)d_in[19];
    const float* W1 = (const float*)d_in[20];
    const float* b1 = (const float*)d_in[21];
    const float* W2 = (const float*)d_in[22];
    const float* b2 = (const float*)d_in[23];
    float* out = (float*)d_out;

    k_init<<<(NN + 255) / 256, 256>>>();
    // CSR build (independent of question path)
    k_deg<<<(NE + 255) / 256, 256>>>(edge_dst);
    k_scan<<<1, 1024>>>();
    k_perm<<<(NE + 255) / 256, 256>>>(edge_src, edge_dst, edge_type, w_comp);
    // question encoding
    k_gx<<<2 * BB * TT, G3>>>(questions, emb_word, Wx_f, bx_f, Wx_b, bx_b);
    k_gru<<<2, G3>>>(questions, Wh_f, bh_f, Wh_b, bh_b);
    k_qg<<<1, 256>>>(W_hg, b_hg);
    // node features from descriptions
    k_nf0<<<(NN * 32 + 255) / 256, 256>>>(node_descs, emb_desc);
    // RGCN: scatter + basis GEMM (+ fused pooling scores)
    k_agg<<<(NN * 32 + 255) / 256, 256>>>();
    k_rgcn<<<1250, 256>>>(bases, rgcn_bias);
    // attention pooling over nodes
    k_max<<<160, 256>>>();
    k_sum<<<256, 256>>>();
    // classifier
    k_hidden<<<1, H1>>>(W1, b1);
    k_logits<<<(NC + 255) / 256, 256>>>(W2, b2, out);
}

// round 2
// speedup vs baseline: 1.2447x; 1.2447x over previous
#include <cuda_runtime.h>
#include <cuda_fp16.h>
#include <math.h>

#define NN 20000
#define NE 320000
#define NR 200
#define DL 16
#define G  64
#define DW 300
#define DH 256
#define HD 128
#define NC 2000
#define BB 4
#define TT 32
#define G3 (3*HD)    // 384
#define BG (BB*G)    // 256
#define H1 1024
#define FEAT (G+DH)  // 320

// ---------------- scratch ----------------
__device__ float g_gx[2][BB][TT][G3];
__device__ float g_qemb[BB][DH];
__device__ float g_qg[BB][G];
__device__ __half2 g_nf0h[NN][BG/2];       // node features (half) [n][b*32 + gpair]
__device__ float g_sacc[NN][BG];
__device__ float g_nf1[NN][BG];
__device__ int   g_deg[NN];
__device__ int   g_off[NN+1];
__device__ int   g_cur[NN];
__device__ int   g_psrc[NE];
__device__ float g_pw[NE];
__device__ float g_scores[BB][NN];
__device__ unsigned g_bmaxU[BB];
__device__ float g_agg[BB][G];
__device__ float g_den[BB];
__device__ float g_hid[BB][H1];

// ---------------- helpers ----------------
__device__ __forceinline__ unsigned fenc(float f) {
    unsigned u = __float_as_uint(f);
    return (u & 0x80000000u) ? ~u : (u | 0x80000000u);
}
__device__ __forceinline__ float fdec(unsigned e) {
    return (e & 0x80000000u) ? __uint_as_float(e & 0x7FFFFFFFu)
                             : __uint_as_float(~e);
}
__device__ __forceinline__ float sigm(float x) { return 1.f / (1.f + __expf(-x)); }
__device__ __forceinline__ float tanh_fast(float x) { return 2.f / (1.f + __expf(-2.f * x)) - 1.f; }

__device__ __forceinline__ void fma2(unsigned long long& d, unsigned long long a,
                                     unsigned long long b, unsigned long long c) {
    asm("fma.rn.f32x2 %0, %1, %2, %3;" : "=l"(d) : "l"(a), "l"(b), "l"(c));
}
__device__ __forceinline__ unsigned long long pk2(float x, float y) {
    unsigned long long r; asm("mov.b64 %0, {%1, %2};" : "=l"(r) : "f"(x), "f"(y)); return r;
}
__device__ __forceinline__ float2 upk2(unsigned long long v) {
    float2 f; asm("mov.b64 {%0, %1}, %2;" : "=f"(f.x), "=f"(f.y) : "l"(v)); return f;
}

// ---------------- kernels ----------------
__global__ void k_init() {
    int i = blockIdx.x * blockDim.x + threadIdx.x;
    if (i < NN) g_deg[i] = 0;
    if (i < BB * G) ((float*)g_agg)[i] = 0.f;
    if (i < BB) { g_den[i] = 0.f; g_bmaxU[i] = 0u; }
}

// input gates gx = x @ Wx + bx.  64 blocks (2 dirs x 32 groups of 4 bt) x 384 threads
__global__ void k_gx(const int* __restrict__ q, const float* __restrict__ embw,
                     const float* __restrict__ WxF, const float* __restrict__ bxF,
                     const float* __restrict__ WxB, const float* __restrict__ bxB) {
    int d = blockIdx.x >> 5;
    int grp = blockIdx.x & 31;
    const float* Wx = d ? WxB : WxF;
    const float* bx = d ? bxB : bxF;
    __shared__ unsigned long long xs01[DW];
    __shared__ unsigned long long xs23[DW];
    int bt0 = grp * 4;
    int tok0 = q[((bt0 + 0) >> 5) * TT + ((bt0 + 0) & 31)];
    int tok1 = q[((bt0 + 1) >> 5) * TT + ((bt0 + 1) & 31)];
    int tok2 = q[((bt0 + 2) >> 5) * TT + ((bt0 + 2) & 31)];
    int tok3 = q[((bt0 + 3) >> 5) * TT + ((bt0 + 3) & 31)];
    for (int k = threadIdx.x; k < DW; k += blockDim.x) {
        float e0 = embw[tok0 * DW + k];
        float e1 = embw[tok1 * DW + k];
        float e2 = embw[tok2 * DW + k];
        float e3 = embw[tok3 * DW + k];
        xs01[k] = pk2(e0, e1);
        xs23[k] = pk2(e2, e3);
    }
    __syncthreads();
    int j = threadIdx.x;
    float bj = bx[j];
    unsigned long long a01 = pk2(bj, bj), a23 = a01;
    #pragma unroll 4
    for (int k = 0; k < DW; k++) {
        float w = Wx[k * G3 + j];
        unsigned long long wd = pk2(w, w);
        fma2(a01, xs01[k], wd, a01);
        fma2(a23, xs23[k], wd, a23);
    }
    float2 f01 = upk2(a01), f23 = upk2(a23);
    g_gx[d][(bt0 + 0) >> 5][(bt0 + 0) & 31][j] = f01.x;
    g_gx[d][(bt0 + 1) >> 5][(bt0 + 1) & 31][j] = f01.y;
    g_gx[d][(bt0 + 2) >> 5][(bt0 + 2) & 31][j] = f23.x;
    g_gx[d][(bt0 + 3) >> 5][(bt0 + 3) & 31][j] = f23.y;
}

// GRU recurrence. 2 blocks x 384 threads, f32x2-packed batch accumulators.
__global__ void k_gru(const int* __restrict__ q,
                      const float* __restrict__ WhF, const float* __restrict__ bhF,
                      const float* __restrict__ WhB, const float* __restrict__ bhB) {
    int d = blockIdx.x;
    const float* Wh = d ? WhB : WhF;
    const float* bh = d ? bhB : bhF;
    __shared__ ulonglong2 hs4[HD];     // per k: (h0,h1),(h2,h3)
    __shared__ float gh[BB][G3];
    int tid = threadIdx.x;
    if (tid < HD) hs4[tid] = make_ulonglong2(0ull, 0ull);
    __syncthreads();
    int j = tid;
    float bj = bh[j];
    unsigned long long bj2 = pk2(bj, bj);
    for (int s = 0; s < TT; s++) {
        int t = d ? (TT - 1 - s) : s;
        unsigned long long a01 = bj2, a23 = bj2;
        #pragma unroll 4
        for (int k = 0; k < HD; k++) {
            float w = Wh[k * G3 + j];
            unsigned long long wd = pk2(w, w);
            ulonglong2 hv = hs4[k];
            fma2(a01, hv.x, wd, a01);
            fma2(a23, hv.y, wd, a23);
        }
        float2 f01 = upk2(a01), f23 = upk2(a23);
        gh[0][j] = f01.x; gh[1][j] = f01.y; gh[2][j] = f23.x; gh[3][j] = f23.y;
        __syncthreads();
        for (int u = tid; u < BB * HD; u += blockDim.x) {
            int b = u >> 7, i = u & 127;
            const float* gx = &g_gx[d][b][t][0];
            float r = sigm(gx[i] + gh[b][i]);
            float z = sigm(gx[HD + i] + gh[b][HD + i]);
            float n = tanh_fast(gx[2 * HD + i] + r * gh[b][2 * HD + i]);
            float hold = ((float*)hs4)[i * 4 + b];
            float hn = (1.f - z) * n + z * hold;
            if (q[b * TT + t] != 0) ((float*)hs4)[i * 4 + b] = hn;
        }
        __syncthreads();
    }
    for (int u = tid; u < BB * HD; u += blockDim.x) {
        int b = u >> 7, i = u & 127;
        g_qemb[b][d * HD + i] = ((float*)hs4)[i * 4 + b];
    }
}

__global__ void k_qg(const float* __restrict__ Whg, const float* __restrict__ bhg) {
    int tid = threadIdx.x;
    int b = tid >> 6, g = tid & 63;
    float acc = bhg[g];
    #pragma unroll 8
    for (int k = 0; k < DH; k++) acc = fmaf(g_qemb[b][k], Whg[k * G + g], acc);
    g_qg[b][g] = acc;
}

// desc attention -> nf0 (half2 output).  one warp per node; scores staged in smem.
__global__ void k_nf0(const int* __restrict__ descs, const float* __restrict__ embd) {
    int warp = (blockIdx.x * blockDim.x + threadIdx.x) >> 5;
    int lane = threadIdx.x & 31;
    int wl = (threadIdx.x >> 5);
    __shared__ float sc_s[8][BB * DL];
    if (warp >= NN) return;
    const int n = warp;
    float qg0[BB], qg1[BB];
    #pragma unroll
    for (int b = 0; b < BB; b++) { qg0[b] = g_qg[b][2 * lane]; qg1[b] = g_qg[b][2 * lane + 1]; }
    float dv0[DL], dv1[DL];
    #pragma unroll
    for (int t = 0; t < DL; t++) {
        int tok = descs[n * DL + t];
        float2 e = *(const float2*)&embd[tok * G + 2 * lane];
        dv0[t] = e.x; dv1[t] = e.y;
        #pragma unroll
        for (int b = 0; b < BB; b++) {
            float p = e.x * qg0[b] + e.y * qg1[b];
            p += __shfl_xor_sync(0xFFFFFFFFu, p, 16);
            p += __shfl_xor_sync(0xFFFFFFFFu, p, 8);
            p += __shfl_xor_sync(0xFFFFFFFFu, p, 4);
            p += __shfl_xor_sync(0xFFFFFFFFu, p, 2);
            p += __shfl_xor_sync(0xFFFFFFFFu, p, 1);
            if (lane == 0) sc_s[wl][b * DL + t] = p;
        }
    }
    __syncwarp();
    #pragma unroll
    for (int b = 0; b < BB; b++) {
        float m = sc_s[wl][b * DL];
        #pragma unroll
        for (int t = 1; t < DL; t++) m = fmaxf(m, sc_s[wl][b * DL + t]);
        float den = 0.f, o0 = 0.f, o1 = 0.f;
        #pragma unroll
        for (int t = 0; t < DL; t++) {
            float w = __expf(sc_s[wl][b * DL + t] - m);
            den += w;
            o0 = fmaf(w, dv0[t], o0);
            o1 = fmaf(w, dv1[t], o1);
        }
        float inv = 1.f / den;
        g_nf0h[n][b * 32 + lane] = __floats2half2_rn(o0 * inv, o1 * inv);
    }
}

__global__ void k_deg(const int* __restrict__ dst) {
    int e = blockIdx.x * blockDim.x + threadIdx.x;
    if (e < NE) atomicAdd(&g_deg[dst[e]], 1);
}

// single-block warp-shfl exclusive scan of degrees
__global__ void k_scan() {
    __shared__ int wsum[32];
    __shared__ int carry;
    int tid = threadIdx.x, lane = tid & 31, wid = tid >> 5;
    if (tid == 0) carry = 0;
    __syncthreads();
    for (int base = 0; base < NN; base += 1024) {
        int idx = base + tid;
        int v = (idx < NN) ? g_deg[idx] : 0;
        int x = v;
        #pragma unroll
        for (int o = 1; o < 32; o <<= 1) {
            int y = __shfl_up_sync(0xFFFFFFFFu, x, o);
            if (lane >= o) x += y;
        }
        if (lane == 31) wsum[wid] = x;
        __syncthreads();
        if (wid == 0) {
            int s = wsum[lane];
            #pragma unroll
            for (int o = 1; o < 32; o <<= 1) {
                int y = __shfl_up_sync(0xFFFFFFFFu, s, o);
                if (lane >= o) s += y;
            }
            wsum[lane] = s;
        }
        __syncthreads();
        int ex = carry + (wid ? wsum[wid - 1] : 0) + x - v;
        if (idx < NN) { g_off[idx] = ex; g_cur[idx] = ex; }
        __syncthreads();
        if (tid == 0) carry += wsum[31];
        __syncthreads();
    }
    if (tid == 0) g_off[NN] = carry;
}

__global__ void k_perm(const int* __restrict__ src, const int* __restrict__ dst,
                       const int* __restrict__ et, const float* __restrict__ wcomp) {
    int e = blockIdx.x * blockDim.x + threadIdx.x;
    if (e >= NE) return;
    int pos = atomicAdd(&g_cur[dst[e]], 1);
    g_psrc[pos] = src[e];
    g_pw[pos]   = wcomp[et[e]];
}

// edge aggregation over half payloads, fp32 accumulate; one warp per dst node
__global__ void k_agg() {
    int warp = (blockIdx.x * blockDim.x + threadIdx.x) >> 5;
    int lane = threadIdx.x & 31;
    if (warp >= NN) return;
    int n = warp;
    int beg = g_off[n], end = g_off[n + 1];
    float a[8] = {0, 0, 0, 0, 0, 0, 0, 0};
    for (int i = beg; i < end; i++) {
        int s = g_psrc[i];
        float w = g_pw[i];
        uint4 v = *(const uint4*)&g_nf0h[s][lane * 4];
        const __half2* hp = (const __half2*)&v;
        #pragma unroll
        for (int qq = 0; qq < 4; qq++) {
            float2 f = __half22float2(hp[qq]);
            a[2 * qq]     = fmaf(w, f.x, a[2 * qq]);
            a[2 * qq + 1] = fmaf(w, f.y, a[2 * qq + 1]);
        }
    }
    float4* op = (float4*)&g_sacc[n][lane * 8];
    op[0] = make_float4(a[0], a[1], a[2], a[3]);
    op[1] = make_float4(a[4], a[5], a[6], a[7]);
}

// nf1 = relu(s @ bases + bias), fused pooling scores + per-block running max
__global__ void k_rgcn(const float* __restrict__ bases, const float* __restrict__ bias) {
    __shared__ float bs[G * G];
    __shared__ float srow[BG];
    __shared__ float swred[8];
    int tid = threadIdx.x;   // 256
    for (int i = tid; i < G * G; i += 256) bs[i] = bases[i];
    int b = tid >> 6, g = tid & 63;
    float bia = bias[g];
    float qv = g_qg[b][g];
    float mloc = -3.0e38f;
    __syncthreads();
    for (int n = blockIdx.x; n < NN; n += gridDim.x) {
        srow[tid] = g_sacc[n][tid];
        __syncthreads();
        float acc = bia;
        const float* sb = &srow[b * G];
        #pragma unroll 8
        for (int k = 0; k < G; k++) acc = fmaf(sb[k], bs[k * G + g], acc);
        acc = fmaxf(acc, 0.f);
        g_nf1[n][tid] = acc;
        float p = acc * qv;
        p += __shfl_xor_sync(0xFFFFFFFFu, p, 16);
        p += __shfl_xor_sync(0xFFFFFFFFu, p, 8);
        p += __shfl_xor_sync(0xFFFFFFFFu, p, 4);
        p += __shfl_xor_sync(0xFFFFFFFFu, p, 2);
        p += __shfl_xor_sync(0xFFFFFFFFu, p, 1);
        if ((tid & 31) == 0) swred[tid >> 5] = p;
        __syncthreads();
        if (tid < BB) {
            float sv = swred[2 * tid] + swred[2 * tid + 1];
            g_scores[tid][n] = sv;
            mloc = fmaxf(mloc, sv);
        }
        __syncthreads();
    }
    if (tid < BB) atomicMax(&g_bmaxU[tid], fenc(mloc));
}

__global__ void k_sum() {
    int tid = threadIdx.x;   // 256: (b,g)
    int b = tid >> 6, g = tid & 63;
    float m = fdec(g_bmaxU[b]);
    float acc = 0.f, den = 0.f;
    for (int n = blockIdx.x; n < NN; n += gridDim.x) {
        float e = __expf(g_scores[b][n] - m);
        acc = fmaf(e, g_nf1[n][tid], acc);
        if (g == 0) den += e;
    }
    atomicAdd(&g_agg[b][g], acc);
    if (g == 0) atomicAdd(&g_den[b], den);
}

__global__ void k_hidden(const float* __restrict__ W1, const float* __restrict__ b1) {
    int tid = threadIdx.x;   // 128
    int h = blockIdx.x * 128 + tid;
    __shared__ float feat[BB][FEAT];
    for (int i = tid; i < BB * FEAT; i += 128) {
        int b = i / FEAT, k = i % FEAT;
        feat[b][k] = (k < G) ? (g_agg[b][k] / g_den[b]) : g_qemb[b][k - G];
    }
    __syncthreads();
    float a0 = b1[h], a1 = a0, a2 = a0, a3 = a0;
    #pragma unroll 4
    for (int k = 0; k < FEAT; k++) {
        float w = W1[k * H1 + h];
        a0 = fmaf(feat[0][k], w, a0);
        a1 = fmaf(feat[1][k], w, a1);
        a2 = fmaf(feat[2][k], w, a2);
        a3 = fmaf(feat[3][k], w, a3);
    }
    g_hid[0][h] = fmaxf(a0, 0.f);
    g_hid[1][h] = fmaxf(a1, 0.f);
    g_hid[2][h] = fmaxf(a2, 0.f);
    g_hid[3][h] = fmaxf(a3, 0.f);
}

// split-K logits: 32 blocks x 256 threads (4 k-parts x 64 classes)
__global__ void k_logits(const float* __restrict__ W2, const float* __restrict__ b2,
                         float* __restrict__ out) {
    __shared__ float hsm[BB][H1];
    __shared__ float red[4][64][4];
    int tid = threadIdx.x;
    for (int i = tid; i < BB * H1; i += 256)
        ((float*)hsm)[i] = ((const float*)g_hid)[i];
    __syncthreads();
    int kp = tid >> 6, cl = tid & 63;
    int c = blockIdx.x * 64 + cl;
    float a0 = 0.f, a1 = 0.f, a2 = 0.f, a3 = 0.f;
    if (c < NC) {
        int k0 = kp * 256;
        #pragma unroll 4
        for (int k = k0; k < k0 + 256; k++) {
            float w = W2[k * NC + c];
            a0 = fmaf(hsm[0][k], w, a0);
            a1 = fmaf(hsm[1][k], w, a1);
            a2 = fmaf(hsm[2][k], w, a2);
            a3 = fmaf(hsm[3][k], w, a3);
        }
    }
    red[kp][cl][0] = a0; red[kp][cl][1] = a1; red[kp][cl][2] = a2; red[kp][cl][3] = a3;
    __syncthreads();
    if (kp == 0 && c < NC) {
        float bb2 = b2[c];
        #pragma unroll
        for (int b = 0; b < BB; b++) {
            float s = bb2 + red[0][cl][b] + red[1][cl][b] + red[2][cl][b] + red[3][cl][b];
            out[b * NC + c] = s;
        }
    }
}

// ---------------- launch ----------------
extern "C" void kernel_launch(void* const* d_in, const int* in_sizes, int n_in,
                              void* d_out, int out_size) {
    const int*   questions = (const int*)d_in[0];
    const int*   node_descs= (const int*)d_in[1];
    const int*   edge_src  = (const int*)d_in[2];
    const int*   edge_dst  = (const int*)d_in[3];
    const int*   edge_type = (const int*)d_in[4];
    const float* emb_word  = (const float*)d_in[5];
    const float* emb_desc  = (const float*)d_in[6];
    const float* Wx_f = (const float*)d_in[7];
    const float* Wh_f = (const float*)d_in[8];
    const float* bx_f = (const float*)d_in[9];
    const float* bh_f = (const float*)d_in[10];
    const float* Wx_b = (const float*)d_in[11];
    const float* Wh_b = (const float*)d_in[12];
    const float* bx_b = (const float*)d_in[13];
    const float* bh_b = (const float*)d_in[14];
    const float* W_hg = (const float*)d_in[15];
    const float* b_hg = (const float*)d_in[16];
    const float* bases = (const float*)d_in[17];
    const float* w_comp = (const float*)d_in[18];
    const float* rgcn_bias = (const float*)d_in[19];
    const float* W1 = (const float*)d_in[20];
    const float* b1 = (const float*)d_in[21];
    const float* W2 = (const float*)d_in[22];
    const float* b2 = (const float*)d_in[23];
    float* out = (float*)d_out;

    // ordering chosen so the ncu single-kernel capture window lands on k_gru
    k_gx<<<64, G3>>>(questions, emb_word, Wx_f, bx_f, Wx_b, bx_b);
    k_init<<<(NN + 255) / 256, 256>>>();
    k_deg<<<(NE + 255) / 256, 256>>>(edge_dst);
    k_gru<<<2, G3>>>(questions, Wh_f, bh_f, Wh_b, bh_b);
    k_scan<<<1, 1024>>>();
    k_perm<<<(NE + 255) / 256, 256>>>(edge_src, edge_dst, edge_type, w_comp);
    k_qg<<<1, 256>>>(W_hg, b_hg);
    k_nf0<<<(NN * 32 + 255) / 256, 256>>>(node_descs, emb_desc);
    k_agg<<<(NN * 32 + 255) / 256, 256>>>();
    k_rgcn<<<1250, 256>>>(bases, rgcn_bias);
    k_sum<<<256, 256>>>();
    k_hidden<<<8, 128>>>(W1, b1);
    k_logits<<<32, 256>>>(W2, b2, out);
}

// round 4
// speedup vs baseline: 1.6357x; 1.3141x over previous
#include <cuda_runtime.h>
#include <cuda_fp16.h>
#include <math.h>

#define NN 20000
#define NE 320000
#define NR 200
#define DL 16
#define G  64
#define DW 300
#define DH 256
#define HD 128
#define NC 2000
#define BB 4
#define TT 32
#define G3 (3*HD)    // 384
#define BG (BB*G)    // 256
#define H1 1024
#define FEAT (G+DH)  // 320

// dynamic smem for k_gru: Wh (HD*G3 floats) + hs4 (HD ulonglong2) + gh (BB*G3 floats)
#define SMEM_GRU (HD*G3*4 + HD*16 + BB*G3*4)   // 196608 + 2048 + 6144 = 204800

// ---------------- scratch ----------------
__device__ float g_gx[2][BB][TT][G3];
__device__ float g_qemb[BB][DH];
__device__ float g_qg[BB][G];
__device__ __half2 g_nf0h[NN][BG/2];       // node features (half) [n][b*32 + gpair]
__device__ float g_sacc[NN][BG];
__device__ float g_nf1[NN][BG];
__device__ int   g_deg[NN];
__device__ int   g_off[NN+1];
__device__ int   g_cur[NN];
__device__ int   g_psrc[NE];
__device__ float g_pw[NE];
__device__ float g_scores[BB][NN];
__device__ unsigned g_bmaxU[BB];
__device__ float g_agg[BB][G];
__device__ float g_den[BB];
__device__ float g_hid[BB][H1];

// ---------------- helpers ----------------
__device__ __forceinline__ unsigned fenc(float f) {
    unsigned u = __float_as_uint(f);
    return (u & 0x80000000u) ? ~u : (u | 0x80000000u);
}
__device__ __forceinline__ float fdec(unsigned e) {
    return (e & 0x80000000u) ? __uint_as_float(e & 0x7FFFFFFFu)
                             : __uint_as_float(~e);
}
__device__ __forceinline__ float sigm(float x) { return 1.f / (1.f + __expf(-x)); }
__device__ __forceinline__ float tanh_fast(float x) { return 2.f / (1.f + __expf(-2.f * x)) - 1.f; }

__device__ __forceinline__ void fma2(unsigned long long& d, unsigned long long a,
                                     unsigned long long b, unsigned long long c) {
    asm("fma.rn.f32x2 %0, %1, %2, %3;" : "=l"(d) : "l"(a), "l"(b), "l"(c));
}
__device__ __forceinline__ unsigned long long pk2(float x, float y) {
    unsigned long long r; asm("mov.b64 %0, {%1, %2};" : "=l"(r) : "f"(x), "f"(y)); return r;
}
__device__ __forceinline__ float2 upk2(unsigned long long v) {
    float2 f; asm("mov.b64 {%0, %1}, %2;" : "=f"(f.x), "=f"(f.y) : "l"(v)); return f;
}

// ---------------- kernels ----------------
__global__ void k_init() {
    int i = blockIdx.x * blockDim.x + threadIdx.x;
    if (i < NN) g_deg[i] = 0;
    if (i < BB * G) ((float*)g_agg)[i] = 0.f;
    if (i < BB) { g_den[i] = 0.f; g_bmaxU[i] = 0u; }
}

// input gates gx = x @ Wx + bx.  64 blocks (2 dirs x 32 groups of 4 bt) x 384 threads
__global__ void k_gx(const int* __restrict__ q, const float* __restrict__ embw,
                     const float* __restrict__ WxF, const float* __restrict__ bxF,
                     const float* __restrict__ WxB, const float* __restrict__ bxB) {
    int d = blockIdx.x >> 5;
    int grp = blockIdx.x & 31;
    const float* Wx = d ? WxB : WxF;
    const float* bx = d ? bxB : bxF;
    __shared__ unsigned long long xs01[DW];
    __shared__ unsigned long long xs23[DW];
    int bt0 = grp * 4;
    int tok0 = q[((bt0 + 0) >> 5) * TT + ((bt0 + 0) & 31)];
    int tok1 = q[((bt0 + 1) >> 5) * TT + ((bt0 + 1) & 31)];
    int tok2 = q[((bt0 + 2) >> 5) * TT + ((bt0 + 2) & 31)];
    int tok3 = q[((bt0 + 3) >> 5) * TT + ((bt0 + 3) & 31)];
    for (int k = threadIdx.x; k < DW; k += blockDim.x) {
        float e0 = embw[tok0 * DW + k];
        float e1 = embw[tok1 * DW + k];
        float e2 = embw[tok2 * DW + k];
        float e3 = embw[tok3 * DW + k];
        xs01[k] = pk2(e0, e1);
        xs23[k] = pk2(e2, e3);
    }
    __syncthreads();
    int j = threadIdx.x;
    float bj = bx[j];
    unsigned long long a01 = pk2(bj, bj), a23 = a01;
    #pragma unroll 4
    for (int k = 0; k < DW; k++) {
        float w = Wx[k * G3 + j];
        unsigned long long wd = pk2(w, w);
        fma2(a01, xs01[k], wd, a01);
        fma2(a23, xs23[k], wd, a23);
    }
    float2 f01 = upk2(a01), f23 = upk2(a23);
    g_gx[d][(bt0 + 0) >> 5][(bt0 + 0) & 31][j] = f01.x;
    g_gx[d][(bt0 + 1) >> 5][(bt0 + 1) & 31][j] = f01.y;
    g_gx[d][(bt0 + 2) >> 5][(bt0 + 2) & 31][j] = f23.x;
    g_gx[d][(bt0 + 3) >> 5][(bt0 + 3) & 31][j] = f23.y;
}

// GRU recurrence. 2 blocks x 384 threads. Wh staged ONCE into dynamic smem
// (196KB) — inner loop is pure LDS + FFMA2, no global traffic per step.
__global__ __launch_bounds__(G3, 1) void k_gru(const int* __restrict__ q,
                      const float* __restrict__ WhF, const float* __restrict__ bhF,
                      const float* __restrict__ WhB, const float* __restrict__ bhB) {
    extern __shared__ float sm[];
    float* Wh_s = sm;                                   // [HD*G3]
    ulonglong2* hs4 = (ulonglong2*)(sm + HD * G3);      // [HD]: (h0,h1),(h2,h3)
    float* gh = (float*)(hs4 + HD);                     // [BB][G3]
    int d = blockIdx.x;
    const float* Wh = d ? WhB : WhF;
    const float* bh = d ? bhB : bhF;
    int tid = threadIdx.x;
    // stage Wh (49152 floats) as float4
    {
        const float4* src = (const float4*)Wh;
        float4* dst = (float4*)Wh_s;
        #pragma unroll
        for (int i = 0; i < (HD * G3 / 4) / G3; i++)
            dst[i * G3 + tid] = src[i * G3 + tid];
    }
    if (tid < HD) hs4[tid] = make_ulonglong2(0ull, 0ull);
    __syncthreads();
    int j = tid;
    float bj = bh[j];
    unsigned long long bj2 = pk2(bj, bj);
    for (int s = 0; s < TT; s++) {
        int t = d ? (TT - 1 - s) : s;
        unsigned long long a01 = bj2, a23 = bj2;
        #pragma unroll 8
        for (int k = 0; k < HD; k++) {
            float w = Wh_s[k * G3 + j];
            unsigned long long wd = pk2(w, w);
            ulonglong2 hv = hs4[k];
            fma2(a01, hv.x, wd, a01);
            fma2(a23, hv.y, wd, a23);
        }
        float2 f01 = upk2(a01), f23 = upk2(a23);
        gh[0 * G3 + j] = f01.x; gh[1 * G3 + j] = f01.y;
        gh[2 * G3 + j] = f23.x; gh[3 * G3 + j] = f23.y;
        __syncthreads();
        for (int u = tid; u < BB * HD; u += G3) {
            int b = u >> 7, i = u & 127;
            const float* gx = &g_gx[d][b][t][0];
            float r = sigm(gx[i] + gh[b * G3 + i]);
            float z = sigm(gx[HD + i] + gh[b * G3 + HD + i]);
            float n = tanh_fast(gx[2 * HD + i] + r * gh[b * G3 + 2 * HD + i]);
            float hold = ((float*)hs4)[i * 4 + b];
            float hn = (1.f - z) * n + z * hold;
            if (q[b * TT + t] != 0) ((float*)hs4)[i * 4 + b] = hn;
        }
        __syncthreads();
    }
    for (int u = tid; u < BB * HD; u += G3) {
        int b = u >> 7, i = u & 127;
        g_qemb[b][d * HD + i] = ((float*)hs4)[i * 4 + b];
    }
}

__global__ void k_qg(const float* __restrict__ Whg, const float* __restrict__ bhg) {
    int tid = threadIdx.x;
    int b = tid >> 6, g = tid & 63;
    float acc = bhg[g];
    #pragma unroll 8
    for (int k = 0; k < DH; k++) acc = fmaf(g_qemb[b][k], Whg[k * G + g], acc);
    g_qg[b][g] = acc;
}

// desc attention -> nf0 (half2 output).  one warp per node; scores staged in smem.
__global__ void k_nf0(const int* __restrict__ descs, const float* __restrict__ embd) {
    int warp = (blockIdx.x * blockDim.x + threadIdx.x) >> 5;
    int lane = threadIdx.x & 31;
    int wl = (threadIdx.x >> 5);
    __shared__ float sc_s[8][BB * DL];
    if (warp >= NN) return;
    const int n = warp;
    float qg0[BB], qg1[BB];
    #pragma unroll
    for (int b = 0; b < BB; b++) { qg0[b] = g_qg[b][2 * lane]; qg1[b] = g_qg[b][2 * lane + 1]; }
    float dv0[DL], dv1[DL];
    #pragma unroll
    for (int t = 0; t < DL; t++) {
        int tok = descs[n * DL + t];
        float2 e = *(const float2*)&embd[tok * G + 2 * lane];
        dv0[t] = e.x; dv1[t] = e.y;
        #pragma unroll
        for (int b = 0; b < BB; b++) {
            float p = e.x * qg0[b] + e.y * qg1[b];
            p += __shfl_xor_sync(0xFFFFFFFFu, p, 16);
            p += __shfl_xor_sync(0xFFFFFFFFu, p, 8);
            p += __shfl_xor_sync(0xFFFFFFFFu, p, 4);
            p += __shfl_xor_sync(0xFFFFFFFFu, p, 2);
            p += __shfl_xor_sync(0xFFFFFFFFu, p, 1);
            if (lane == 0) sc_s[wl][b * DL + t] = p;
        }
    }
    __syncwarp();
    #pragma unroll
    for (int b = 0; b < BB; b++) {
        float m = sc_s[wl][b * DL];
        #pragma unroll
        for (int t = 1; t < DL; t++) m = fmaxf(m, sc_s[wl][b * DL + t]);
        float den = 0.f, o0 = 0.f, o1 = 0.f;
        #pragma unroll
        for (int t = 0; t < DL; t++) {
            float w = __expf(sc_s[wl][b * DL + t] - m);
            den += w;
            o0 = fmaf(w, dv0[t], o0);
            o1 = fmaf(w, dv1[t], o1);
        }
        float inv = 1.f / den;
        g_nf0h[n][b * 32 + lane] = __floats2half2_rn(o0 * inv, o1 * inv);
    }
}

__global__ void k_deg(const int* __restrict__ dst) {
    int e = blockIdx.x * blockDim.x + threadIdx.x;
    if (e < NE) atomicAdd(&g_deg[dst[e]], 1);
}

// single-block warp-shfl exclusive scan of degrees
__global__ void k_scan() {
    __shared__ int wsum[32];
    __shared__ int carry;
    int tid = threadIdx.x, lane = tid & 31, wid = tid >> 5;
    if (tid == 0) carry = 0;
    __syncthreads();
    for (int base = 0; base < NN; base += 1024) {
        int idx = base + tid;
        int v = (idx < NN) ? g_deg[idx] : 0;
        int x = v;
        #pragma unroll
        for (int o = 1; o < 32; o <<= 1) {
            int y = __shfl_up_sync(0xFFFFFFFFu, x, o);
            if (lane >= o) x += y;
        }
        if (lane == 31) wsum[wid] = x;
        __syncthreads();
        if (wid == 0) {
            int s = wsum[lane];
            #pragma unroll
            for (int o = 1; o < 32; o <<= 1) {
                int y = __shfl_up_sync(0xFFFFFFFFu, s, o);
                if (lane >= o) s += y;
            }
            wsum[lane] = s;
        }
        __syncthreads();
        int ex = carry + (wid ? wsum[wid - 1] : 0) + x - v;
        if (idx < NN) { g_off[idx] = ex; g_cur[idx] = ex; }
        __syncthreads();
        if (tid == 0) carry += wsum[31];
        __syncthreads();
    }
    if (tid == 0) g_off[NN] = carry;
}

__global__ void k_perm(const int* __restrict__ src, const int* __restrict__ dst,
                       const int* __restrict__ et, const float* __restrict__ wcomp) {
    int e = blockIdx.x * blockDim.x + threadIdx.x;
    if (e >= NE) return;
    int pos = atomicAdd(&g_cur[dst[e]], 1);
    g_psrc[pos] = src[e];
    g_pw[pos]   = wcomp[et[e]];
}

// edge aggregation over half payloads, fp32 accumulate; one warp per dst node
__global__ void k_agg() {
    int warp = (blockIdx.x * blockDim.x + threadIdx.x) >> 5;
    int lane = threadIdx.x & 31;
    if (warp >= NN) return;
    int n = warp;
    int beg = g_off[n], end = g_off[n + 1];
    float a[8] = {0, 0, 0, 0, 0, 0, 0, 0};
    for (int i = beg; i < end; i++) {
        int s = g_psrc[i];
        float w = g_pw[i];
        uint4 v = *(const uint4*)&g_nf0h[s][lane * 4];
        const __half2* hp = (const __half2*)&v;
        #pragma unroll
        for (int qq = 0; qq < 4; qq++) {
            float2 f = __half22float2(hp[qq]);
            a[2 * qq]     = fmaf(w, f.x, a[2 * qq]);
            a[2 * qq + 1] = fmaf(w, f.y, a[2 * qq + 1]);
        }
    }
    float4* op = (float4*)&g_sacc[n][lane * 8];
    op[0] = make_float4(a[0], a[1], a[2], a[3]);
    op[1] = make_float4(a[4], a[5], a[6], a[7]);
}

// nf1 = relu(s @ bases + bias), fused pooling scores + per-block running max
__global__ void k_rgcn(const float* __restrict__ bases, const float* __restrict__ bias) {
    __shared__ float bs[G * G];
    __shared__ float srow[BG];
    __shared__ float swred[8];
    int tid = threadIdx.x;   // 256
    for (int i = tid; i < G * G; i += 256) bs[i] = bases[i];
    int b = tid >> 6, g = tid & 63;
    float bia = bias[g];
    float qv = g_qg[b][g];
    float mloc = -3.0e38f;
    __syncthreads();
    for (int n = blockIdx.x; n < NN; n += gridDim.x) {
        srow[tid] = g_sacc[n][tid];
        __syncthreads();
        float acc = bia;
        const float* sb = &srow[b * G];
        #pragma unroll 8
        for (int k = 0; k < G; k++) acc = fmaf(sb[k], bs[k * G + g], acc);
        acc = fmaxf(acc, 0.f);
        g_nf1[n][tid] = acc;
        float p = acc * qv;
        p += __shfl_xor_sync(0xFFFFFFFFu, p, 16);
        p += __shfl_xor_sync(0xFFFFFFFFu, p, 8);
        p += __shfl_xor_sync(0xFFFFFFFFu, p, 4);
        p += __shfl_xor_sync(0xFFFFFFFFu, p, 2);
        p += __shfl_xor_sync(0xFFFFFFFFu, p, 1);
        if ((tid & 31) == 0) swred[tid >> 5] = p;
        __syncthreads();
        if (tid < BB) {
            float sv = swred[2 * tid] + swred[2 * tid + 1];
            g_scores[tid][n] = sv;
            mloc = fmaxf(mloc, sv);
        }
        __syncthreads();
    }
    if (tid < BB) atomicMax(&g_bmaxU[tid], fenc(mloc));
}

__global__ void k_sum() {
    int tid = threadIdx.x;   // 256: (b,g)
    int b = tid >> 6, g = tid & 63;
    float m = fdec(g_bmaxU[b]);
    float acc = 0.f, den = 0.f;
    for (int n = blockIdx.x; n < NN; n += gridDim.x) {
        float e = __expf(g_scores[b][n] - m);
        acc = fmaf(e, g_nf1[n][tid], acc);
        if (g == 0) den += e;
    }
    atomicAdd(&g_agg[b][g], acc);
    if (g == 0) atomicAdd(&g_den[b], den);
}

__global__ void k_hidden(const float* __restrict__ W1, const float* __restrict__ b1) {
    int tid = threadIdx.x;   // 128
    int h = blockIdx.x * 128 + tid;
    __shared__ float feat[BB][FEAT];
    for (int i = tid; i < BB * FEAT; i += 128) {
        int b = i / FEAT, k = i % FEAT;
        feat[b][k] = (k < G) ? (g_agg[b][k] / g_den[b]) : g_qemb[b][k - G];
    }
    __syncthreads();
    float a0 = b1[h], a1 = a0, a2 = a0, a3 = a0;
    #pragma unroll 4
    for (int k = 0; k < FEAT; k++) {
        float w = W1[k * H1 + h];
        a0 = fmaf(feat[0][k], w, a0);
        a1 = fmaf(feat[1][k], w, a1);
        a2 = fmaf(feat[2][k], w, a2);
        a3 = fmaf(feat[3][k], w, a3);
    }
    g_hid[0][h] = fmaxf(a0, 0.f);
    g_hid[1][h] = fmaxf(a1, 0.f);
    g_hid[2][h] = fmaxf(a2, 0.f);
    g_hid[3][h] = fmaxf(a3, 0.f);
}

// split-K logits: 32 blocks x 256 threads (4 k-parts x 64 classes)
__global__ void k_logits(const float* __restrict__ W2, const float* __restrict__ b2,
                         float* __restrict__ out) {
    __shared__ float hsm[BB][H1];
    __shared__ float red[4][64][4];
    int tid = threadIdx.x;
    for (int i = tid; i < BB * H1; i += 256)
        ((float*)hsm)[i] = ((const float*)g_hid)[i];
    __syncthreads();
    int kp = tid >> 6, cl = tid & 63;
    int c = blockIdx.x * 64 + cl;
    float a0 = 0.f, a1 = 0.f, a2 = 0.f, a3 = 0.f;
    if (c < NC) {
        int k0 = kp * 256;
        #pragma unroll 4
        for (int k = k0; k < k0 + 256; k++) {
            float w = W2[k * NC + c];
            a0 = fmaf(hsm[0][k], w, a0);
            a1 = fmaf(hsm[1][k], w, a1);
            a2 = fmaf(hsm[2][k], w, a2);
            a3 = fmaf(hsm[3][k], w, a3);
        }
    }
    red[kp][cl][0] = a0; red[kp][cl][1] = a1; red[kp][cl][2] = a2; red[kp][cl][3] = a3;
    __syncthreads();
    if (kp == 0 && c < NC) {
        float bb2 = b2[c];
        #pragma unroll
        for (int b = 0; b < BB; b++) {
            float s = bb2 + red[0][cl][b] + red[1][cl][b] + red[2][cl][b] + red[3][cl][b];
            out[b * NC + c] = s;
        }
    }
}

// ---------------- launch ----------------
extern "C" void kernel_launch(void* const* d_in, const int* in_sizes, int n_in,
                              void* d_out, int out_size) {
    const int*   questions = (const int*)d_in[0];
    const int*   node_descs= (const int*)d_in[1];
    const int*   edge_src  = (const int*)d_in[2];
    const int*   edge_dst  = (const int*)d_in[3];
    const int*   edge_type = (const int*)d_in[4];
    const float* emb_word  = (const float*)d_in[5];
    const float* emb_desc  = (const float*)d_in[6];
    const float* Wx_f = (const float*)d_in[7];
    const float* Wh_f = (const float*)d_in[8];
    const float* bx_f = (const float*)d_in[9];
    const float* bh_f = (const float*)d_in[10];
    const float* Wx_b = (const float*)d_in[11];
    const float* Wh_b = (const float*)d_in[12];
    const float* bx_b = (const float*)d_in[13];
    const float* bh_b = (const float*)d_in[14];
    const float* W_hg = (const float*)d_in[15];
    const float* b_hg = (const float*)d_in[16];
    const float* bases = (const float*)d_in[17];
    const float* w_comp = (const float*)d_in[18];
    const float* rgcn_bias = (const float*)d_in[19];
    const float* W1 = (const float*)d_in[20];
    const float* b1 = (const float*)d_in[21];
    const float* W2 = (const float*)d_in[22];
    const float* b2 = (const float*)d_in[23];
    float* out = (float*)d_out;

    static int smem_set = 0;
    if (!smem_set) {
        cudaFuncSetAttribute(k_gru, cudaFuncAttributeMaxDynamicSharedMemorySize, SMEM_GRU);
        smem_set = 1;
    }

    // order: capture slot (4th launch) lands on k_nf0 for next-round profiling
    k_gx<<<64, G3>>>(questions, emb_word, Wx_f, bx_f, Wx_b, bx_b);
    k_gru<<<2, G3, SMEM_GRU>>>(questions, Wh_f, bh_f, Wh_b, bh_b);
    k_qg<<<1, 256>>>(W_hg, b_hg);
    k_nf0<<<(NN * 32 + 255) / 256, 256>>>(node_descs, emb_desc);
    k_init<<<(NN + 255) / 256, 256>>>();
    k_deg<<<(NE + 255) / 256, 256>>>(edge_dst);
    k_scan<<<1, 1024>>>();
    k_perm<<<(NE + 255) / 256, 256>>>(edge_src, edge_dst, edge_type, w_comp);
    k_agg<<<(NN * 32 + 255) / 256, 256>>>();
    k_rgcn<<<1250, 256>>>(bases, rgcn_bias);
    k_sum<<<256, 256>>>();
    k_hidden<<<8, 128>>>(W1, b1);
    k_logits<<<32, 256>>>(W2, b2, out);
}

// round 5
// speedup vs baseline: 2.0602x; 1.2595x over previous
#include <cuda_runtime.h>
#include <cuda_fp16.h>
#include <math.h>

#define NN 20000
#define NE 320000
#define NR 200
#define DL 16
#define G  64
#define DW 300
#define DH 256
#define HD 128
#define NC 2000
#define BB 4
#define TT 32
#define G3 (3*HD)    // 384
#define BG (BB*G)    // 256
#define H1 1024
#define FEAT (G+DH)  // 320

// k_gru dynamic smem: gx (BB*TT*G3 f) + hs4 (HD ull2) + gh (BB*G3 f) + msk (BB*TT i)
#define SMEM_GRU (BB*TT*G3*4 + HD*16 + BB*G3*4 + BB*TT*4)   // 205312

// ---------------- scratch ----------------
__device__ float g_gx[2][BB][TT][G3];
__device__ float g_qemb[BB][DH];
__device__ float g_qg[BB][G];
__device__ __half2 g_nf0h[NN][BG/2];
__device__ float g_sacc[NN][BG];
__device__ float g_nf1[NN][BG];
__device__ int   g_deg[NN];          // statically zero; re-zeroed by k_scan each run
__device__ int   g_off[NN+1];
__device__ int   g_cur[NN];
__device__ int   g_psrc[NE];
__device__ float g_pw[NE];
__device__ float g_scores[BB][NN];
__device__ unsigned g_bmaxU[BB];     // zeroed by k_logits tail
__device__ float g_agg[BB][G];       // zeroed by k_logits tail
__device__ float g_den[BB];          // zeroed by k_logits tail
__device__ float g_hidp[4][BB][H1];  // k-split partials (fully overwritten)

// ---------------- helpers ----------------
__device__ __forceinline__ unsigned fenc(float f) {
    unsigned u = __float_as_uint(f);
    return (u & 0x80000000u) ? ~u : (u | 0x80000000u);
}
__device__ __forceinline__ float fdec(unsigned e) {
    return (e & 0x80000000u) ? __uint_as_float(e & 0x7FFFFFFFu)
                             : __uint_as_float(~e);
}
__device__ __forceinline__ float sigm(float x) { return 1.f / (1.f + __expf(-x)); }
__device__ __forceinline__ float tanh_fast(float x) { return 2.f / (1.f + __expf(-2.f * x)) - 1.f; }

__device__ __forceinline__ void fma2(unsigned long long& d, unsigned long long a,
                                     unsigned long long b, unsigned long long c) {
    asm("fma.rn.f32x2 %0, %1, %2, %3;" : "=l"(d) : "l"(a), "l"(b), "l"(c));
}
__device__ __forceinline__ unsigned long long pk2(float x, float y) {
    unsigned long long r; asm("mov.b64 %0, {%1, %2};" : "=l"(r) : "f"(x), "f"(y)); return r;
}
__device__ __forceinline__ float2 upk2(unsigned long long v) {
    float2 f; asm("mov.b64 {%0, %1}, %2;" : "=f"(f.x), "=f"(f.y) : "l"(v)); return f;
}

// ---------------- kernels ----------------

// input gates gx = x @ Wx + bx.  64 blocks (2 dirs x 32 groups of 4 bt) x 384 threads
__global__ void k_gx(const int* __restrict__ q, const float* __restrict__ embw,
                     const float* __restrict__ WxF, const float* __restrict__ bxF,
                     const float* __restrict__ WxB, const float* __restrict__ bxB) {
    int d = blockIdx.x >> 5;
    int grp = blockIdx.x & 31;
    const float* Wx = d ? WxB : WxF;
    const float* bx = d ? bxB : bxF;
    __shared__ unsigned long long xs01[DW];
    __shared__ unsigned long long xs23[DW];
    int bt0 = grp * 4;
    int tok0 = q[((bt0 + 0) >> 5) * TT + ((bt0 + 0) & 31)];
    int tok1 = q[((bt0 + 1) >> 5) * TT + ((bt0 + 1) & 31)];
    int tok2 = q[((bt0 + 2) >> 5) * TT + ((bt0 + 2) & 31)];
    int tok3 = q[((bt0 + 3) >> 5) * TT + ((bt0 + 3) & 31)];
    for (int k = threadIdx.x; k < DW; k += blockDim.x) {
        float e0 = embw[tok0 * DW + k];
        float e1 = embw[tok1 * DW + k];
        float e2 = embw[tok2 * DW + k];
        float e3 = embw[tok3 * DW + k];
        xs01[k] = pk2(e0, e1);
        xs23[k] = pk2(e2, e3);
    }
    __syncthreads();
    int j = threadIdx.x;
    float bj = bx[j];
    unsigned long long a01 = pk2(bj, bj), a23 = a01;
    #pragma unroll 4
    for (int k = 0; k < DW; k++) {
        float w = Wx[k * G3 + j];
        unsigned long long wd = pk2(w, w);
        fma2(a01, xs01[k], wd, a01);
        fma2(a23, xs23[k], wd, a23);
    }
    float2 f01 = upk2(a01), f23 = upk2(a23);
    g_gx[d][(bt0 + 0) >> 5][(bt0 + 0) & 31][j] = f01.x;
    g_gx[d][(bt0 + 1) >> 5][(bt0 + 1) & 31][j] = f01.y;
    g_gx[d][(bt0 + 2) >> 5][(bt0 + 2) & 31][j] = f23.x;
    g_gx[d][(bt0 + 3) >> 5][(bt0 + 3) & 31][j] = f23.y;
}

// GRU recurrence. 2 blocks x 384 threads. Wh register-resident (128 f/thread);
// gx + masks staged in smem so the per-step path never touches global memory.
__global__ __launch_bounds__(G3, 1) void k_gru(const int* __restrict__ q,
                      const float* __restrict__ WhF, const float* __restrict__ bhF,
                      const float* __restrict__ WhB, const float* __restrict__ bhB) {
    extern __shared__ float sm[];
    float* gx_s = sm;                                       // [BB*TT*G3]
    ulonglong2* hs4 = (ulonglong2*)(sm + BB * TT * G3);     // [HD]
    float* gh = (float*)(hs4 + HD);                         // [BB*G3]
    int* msk = (int*)(gh + BB * G3);                        // [BB*TT]
    int d = blockIdx.x;
    const float* Wh = d ? WhB : WhF;
    const float* bh = d ? bhB : bhF;
    int tid = threadIdx.x;
    // stage gx for this direction (49152 floats)
    {
        const float4* src = (const float4*)&g_gx[d][0][0][0];
        float4* dst = (float4*)gx_s;
        #pragma unroll
        for (int i = 0; i < 32; i++) dst[i * G3 + tid] = src[i * G3 + tid];
    }
    if (tid < BB * TT) msk[tid] = (q[tid] != 0);   // q is [BB][TT] row-major; tid = b*32+t
    if (tid < HD) hs4[tid] = make_ulonglong2(0ull, 0ull);
    // weights into registers
    float w[HD];
    #pragma unroll
    for (int k = 0; k < HD; k++) w[k] = Wh[k * G3 + tid];
    float bj = bh[tid];
    unsigned long long bj2 = pk2(bj, bj);
    __syncthreads();
    for (int s = 0; s < TT; s++) {
        int t = d ? (TT - 1 - s) : s;
        unsigned long long a01 = bj2, a23 = bj2;
        #pragma unroll
        for (int k = 0; k < HD; k++) {
            unsigned long long wd = pk2(w[k], w[k]);
            ulonglong2 hv = hs4[k];
            fma2(a01, hv.x, wd, a01);
            fma2(a23, hv.y, wd, a23);
        }
        float2 f01 = upk2(a01), f23 = upk2(a23);
        gh[0 * G3 + tid] = f01.x; gh[1 * G3 + tid] = f01.y;
        gh[2 * G3 + tid] = f23.x; gh[3 * G3 + tid] = f23.y;
        __syncthreads();
        for (int u = tid; u < BB * HD; u += G3) {
            int b = u >> 7, i = u & 127;
            const float* gx = &gx_s[(b * TT + t) * G3];
            float r = sigm(gx[i] + gh[b * G3 + i]);
            float z = sigm(gx[HD + i] + gh[b * G3 + HD + i]);
            float n = tanh_fast(gx[2 * HD + i] + r * gh[b * G3 + 2 * HD + i]);
            float hold = ((float*)hs4)[i * 4 + b];
            float hn = (1.f - z) * n + z * hold;
            if (msk[b * TT + t]) ((float*)hs4)[i * 4 + b] = hn;
        }
        __syncthreads();
    }
    for (int u = tid; u < BB * HD; u += G3) {
        int b = u >> 7, i = u & 127;
        g_qemb[b][d * HD + i] = ((float*)hs4)[i * 4 + b];
    }
}

__global__ void k_qg(const float* __restrict__ Whg, const float* __restrict__ bhg) {
    int tid = threadIdx.x;
    int b = tid >> 6, g = tid & 63;
    float acc = bhg[g];
    #pragma unroll 8
    for (int k = 0; k < DH; k++) acc = fmaf(g_qemb[b][k], Whg[k * G + g], acc);
    g_qg[b][g] = acc;
}

// desc attention -> nf0 (half2 output).  one warp per node.
__global__ void k_nf0(const int* __restrict__ descs, const float* __restrict__ embd) {
    int warp = (blockIdx.x * blockDim.x + threadIdx.x) >> 5;
    int lane = threadIdx.x & 31;
    int wl = (threadIdx.x >> 5);
    __shared__ float sc_s[8][BB * DL];
    if (warp >= NN) return;
    const int n = warp;
    float qg0[BB], qg1[BB];
    #pragma unroll
    for (int b = 0; b < BB; b++) { qg0[b] = g_qg[b][2 * lane]; qg1[b] = g_qg[b][2 * lane + 1]; }
    float dv0[DL], dv1[DL];
    #pragma unroll
    for (int t = 0; t < DL; t++) {
        int tok = descs[n * DL + t];
        float2 e = *(const float2*)&embd[tok * G + 2 * lane];
        dv0[t] = e.x; dv1[t] = e.y;
        #pragma unroll
        for (int b = 0; b < BB; b++) {
            float p = e.x * qg0[b] + e.y * qg1[b];
            p += __shfl_xor_sync(0xFFFFFFFFu, p, 16);
            p += __shfl_xor_sync(0xFFFFFFFFu, p, 8);
            p += __shfl_xor_sync(0xFFFFFFFFu, p, 4);
            p += __shfl_xor_sync(0xFFFFFFFFu, p, 2);
            p += __shfl_xor_sync(0xFFFFFFFFu, p, 1);
            if (lane == 0) sc_s[wl][b * DL + t] = p;
        }
    }
    __syncwarp();
    #pragma unroll
    for (int b = 0; b < BB; b++) {
        float m = sc_s[wl][b * DL];
        #pragma unroll
        for (int t = 1; t < DL; t++) m = fmaxf(m, sc_s[wl][b * DL + t]);
        float den = 0.f, o0 = 0.f, o1 = 0.f;
        #pragma unroll
        for (int t = 0; t < DL; t++) {
            float w = __expf(sc_s[wl][b * DL + t] - m);
            den += w;
            o0 = fmaf(w, dv0[t], o0);
            o1 = fmaf(w, dv1[t], o1);
        }
        float inv = 1.f / den;
        g_nf0h[n][b * 32 + lane] = __floats2half2_rn(o0 * inv, o1 * inv);
    }
}

__global__ void k_deg(const int* __restrict__ dst) {
    int e = blockIdx.x * blockDim.x + threadIdx.x;
    if (e < NE) atomicAdd(&g_deg[dst[e]], 1);
}

// single-block warp-shfl exclusive scan; re-zeroes g_deg for the next replay
__global__ void k_scan() {
    __shared__ int wsum[32];
    __shared__ int carry;
    int tid = threadIdx.x, lane = tid & 31, wid = tid >> 5;
    if (tid == 0) carry = 0;
    __syncthreads();
    for (int base = 0; base < NN; base += 1024) {
        int idx = base + tid;
        int v = (idx < NN) ? g_deg[idx] : 0;
        if (idx < NN) g_deg[idx] = 0;
        int x = v;
        #pragma unroll
        for (int o = 1; o < 32; o <<= 1) {
            int y = __shfl_up_sync(0xFFFFFFFFu, x, o);
            if (lane >= o) x += y;
        }
        if (lane == 31) wsum[wid] = x;
        __syncthreads();
        if (wid == 0) {
            int s = wsum[lane];
            #pragma unroll
            for (int o = 1; o < 32; o <<= 1) {
                int y = __shfl_up_sync(0xFFFFFFFFu, s, o);
                if (lane >= o) s += y;
            }
            wsum[lane] = s;
        }
        __syncthreads();
        int ex = carry + (wid ? wsum[wid - 1] : 0) + x - v;
        if (idx < NN) { g_off[idx] = ex; g_cur[idx] = ex; }
        __syncthreads();
        if (tid == 0) carry += wsum[31];
        __syncthreads();
    }
    if (tid == 0) g_off[NN] = carry;
}

__global__ void k_perm(const int* __restrict__ src, const int* __restrict__ dst,
                       const int* __restrict__ et, const float* __restrict__ wcomp) {
    int e = blockIdx.x * blockDim.x + threadIdx.x;
    if (e >= NE) return;
    int pos = atomicAdd(&g_cur[dst[e]], 1);
    g_psrc[pos] = src[e];
    g_pw[pos]   = wcomp[et[e]];
}

// edge aggregation over half payloads, fp32 accumulate; one warp per dst node
__global__ void k_agg() {
    int warp = (blockIdx.x * blockDim.x + threadIdx.x) >> 5;
    int lane = threadIdx.x & 31;
    if (warp >= NN) return;
    int n = warp;
    int beg = g_off[n], end = g_off[n + 1];
    float a[8] = {0, 0, 0, 0, 0, 0, 0, 0};
    for (int i = beg; i < end; i++) {
        int s = g_psrc[i];
        float w = g_pw[i];
        uint4 v = *(const uint4*)&g_nf0h[s][lane * 4];
        const __half2* hp = (const __half2*)&v;
        #pragma unroll
        for (int qq = 0; qq < 4; qq++) {
            float2 f = __half22float2(hp[qq]);
            a[2 * qq]     = fmaf(w, f.x, a[2 * qq]);
            a[2 * qq + 1] = fmaf(w, f.y, a[2 * qq + 1]);
        }
    }
    float4* op = (float4*)&g_sacc[n][lane * 8];
    op[0] = make_float4(a[0], a[1], a[2], a[3]);
    op[1] = make_float4(a[4], a[5], a[6], a[7]);
}

// nf1 = relu(s @ bases + bias), fused pooling scores + per-block running max
__global__ void k_rgcn(const float* __restrict__ bases, const float* __restrict__ bias) {
    __shared__ float bs[G * G];
    __shared__ float srow[BG];
    __shared__ float swred[8];
    int tid = threadIdx.x;   // 256
    for (int i = tid; i < G * G; i += 256) bs[i] = bases[i];
    int b = tid >> 6, g = tid & 63;
    float bia = bias[g];
    float qv = g_qg[b][g];
    float mloc = -3.0e38f;
    __syncthreads();
    for (int n = blockIdx.x; n < NN; n += gridDim.x) {
        srow[tid] = g_sacc[n][tid];
        __syncthreads();
        float acc = bia;
        const float* sb = &srow[b * G];
        #pragma unroll 8
        for (int k = 0; k < G; k++) acc = fmaf(sb[k], bs[k * G + g], acc);
        acc = fmaxf(acc, 0.f);
        g_nf1[n][tid] = acc;
        float p = acc * qv;
        p += __shfl_xor_sync(0xFFFFFFFFu, p, 16);
        p += __shfl_xor_sync(0xFFFFFFFFu, p, 8);
        p += __shfl_xor_sync(0xFFFFFFFFu, p, 4);
        p += __shfl_xor_sync(0xFFFFFFFFu, p, 2);
        p += __shfl_xor_sync(0xFFFFFFFFu, p, 1);
        if ((tid & 31) == 0) swred[tid >> 5] = p;
        __syncthreads();
        if (tid < BB) {
            float sv = swred[2 * tid] + swred[2 * tid + 1];
            g_scores[tid][n] = sv;
            mloc = fmaxf(mloc, sv);
        }
        __syncthreads();
    }
    if (tid < BB) atomicMax(&g_bmaxU[tid], fenc(mloc));
}

__global__ void k_sum() {
    int tid = threadIdx.x;   // 256: (b,g)
    int b = tid >> 6, g = tid & 63;
    float m = fdec(g_bmaxU[b]);
    float acc = 0.f, den = 0.f;
    for (int n = blockIdx.x; n < NN; n += gridDim.x) {
        float e = __expf(g_scores[b][n] - m);
        acc = fmaf(e, g_nf1[n][tid], acc);
        if (g == 0) den += e;
    }
    atomicAdd(&g_agg[b][g], acc);
    if (g == 0) atomicAdd(&g_den[b], den);
}

// hidden partials: 32 blocks = (hblk 0..7) x (kp 0..3); 128 threads
__global__ void k_hidden(const float* __restrict__ W1) {
    int hb = blockIdx.x >> 2, kp = blockIdx.x & 3;
    int tid = threadIdx.x;
    int h = hb * 128 + tid;
    int k0 = kp * 80;
    __shared__ float feat[BB][80];
    for (int i = tid; i < BB * 80; i += 128) {
        int b = i / 80, kk = i % 80, k = k0 + kk;
        feat[b][kk] = (k < G) ? (g_agg[b][k] / g_den[b]) : g_qemb[b][k - G];
    }
    __syncthreads();
    float a0 = 0.f, a1 = 0.f, a2 = 0.f, a3 = 0.f;
    #pragma unroll 4
    for (int kk = 0; kk < 80; kk++) {
        float w = W1[(k0 + kk) * H1 + h];
        a0 = fmaf(feat[0][kk], w, a0);
        a1 = fmaf(feat[1][kk], w, a1);
        a2 = fmaf(feat[2][kk], w, a2);
        a3 = fmaf(feat[3][kk], w, a3);
    }
    g_hidp[kp][0][h] = a0; g_hidp[kp][1][h] = a1;
    g_hidp[kp][2][h] = a2; g_hidp[kp][3][h] = a3;
}

// logits: 63 blocks x 256 (8 k-parts x 32 classes); relu+bias fused in load;
// block 0 re-zeroes the accumulators for the next replay.
__global__ void k_logits(const float* __restrict__ W2, const float* __restrict__ b1,
                         const float* __restrict__ b2, float* __restrict__ out) {
    __shared__ float hsm[BB][H1];
    __shared__ float red[8][32][BB];
    int tid = threadIdx.x;
    for (int i = tid; i < BB * H1; i += 256) {
        int b = i >> 10, k = i & (H1 - 1);
        float v = g_hidp[0][b][k] + g_hidp[1][b][k] + g_hidp[2][b][k] + g_hidp[3][b][k] + b1[k];
        hsm[b][k] = fmaxf(v, 0.f);
    }
    __syncthreads();
    int kp = tid >> 5, cl = tid & 31;
    int c = blockIdx.x * 32 + cl;
    float a0 = 0.f, a1 = 0.f, a2 = 0.f, a3 = 0.f;
    if (c < NC) {
        int k0 = kp * 128;
        #pragma unroll 4
        for (int k = k0; k < k0 + 128; k++) {
            float w = W2[k * NC + c];
            a0 = fmaf(hsm[0][k], w, a0);
            a1 = fmaf(hsm[1][k], w, a1);
            a2 = fmaf(hsm[2][k], w, a2);
            a3 = fmaf(hsm[3][k], w, a3);
        }
    }
    red[kp][cl][0] = a0; red[kp][cl][1] = a1; red[kp][cl][2] = a2; red[kp][cl][3] = a3;
    __syncthreads();
    if (kp == 0 && c < NC) {
        float bb2 = b2[c];
        #pragma unroll
        for (int b = 0; b < BB; b++) {
            float s = bb2;
            #pragma unroll
            for (int p = 0; p < 8; p++) s += red[p][cl][b];
            out[b * NC + c] = s;
        }
    }
    // self-restore accumulators for next replay
    if (blockIdx.x == 0) {
        if (tid < BB * G) ((float*)g_agg)[tid] = 0.f;
        if (tid < BB) { g_den[tid] = 0.f; g_bmaxU[tid] = 0u; }
    }
}

// ---------------- launch ----------------
extern "C" void kernel_launch(void* const* d_in, const int* in_sizes, int n_in,
                              void* d_out, int out_size) {
    const int*   questions = (const int*)d_in[0];
    const int*   node_descs= (const int*)d_in[1];
    const int*   edge_src  = (const int*)d_in[2];
    const int*   edge_dst  = (const int*)d_in[3];
    const int*   edge_type = (const int*)d_in[4];
    const float* emb_word  = (const float*)d_in[5];
    const float* emb_desc  = (const float*)d_in[6];
    const float* Wx_f = (const float*)d_in[7];
    const float* Wh_f = (const float*)d_in[8];
    const float* bx_f = (const float*)d_in[9];
    const float* bh_f = (const float*)d_in[10];
    const float* Wx_b = (const float*)d_in[11];
    const float* Wh_b = (const float*)d_in[12];
    const float* bx_b = (const float*)d_in[13];
    const float* bh_b = (const float*)d_in[14];
    const float* W_hg = (const float*)d_in[15];
    const float* b_hg = (const float*)d_in[16];
    const float* bases = (const float*)d_in[17];
    const float* w_comp = (const float*)d_in[18];
    const float* rgcn_bias = (const float*)d_in[19];
    const float* W1 = (const float*)d_in[20];
    const float* b1 = (const float*)d_in[21];
    const float* W2 = (const float*)d_in[22];
    const float* b2 = (const float*)d_in[23];
    float* out = (float*)d_out;

    static cudaStream_t s1 = nullptr;
    static cudaEvent_t ev0 = nullptr, ev1 = nullptr;
    if (!s1) {
        cudaStreamCreateWithFlags(&s1, cudaStreamNonBlocking);
        cudaEventCreateWithFlags(&ev0, cudaEventDisableTiming);
        cudaEventCreateWithFlags(&ev1, cudaEventDisableTiming);
        cudaFuncSetAttribute(k_gru, cudaFuncAttributeMaxDynamicSharedMemorySize, SMEM_GRU);
    }

    // fork: CSR chain on s1, question path on main stream
    cudaEventRecord(ev0, 0);
    cudaStreamWaitEvent(s1, ev0, 0);

    k_gx<<<64, G3>>>(questions, emb_word, Wx_f, bx_f, Wx_b, bx_b);      // 1
    k_deg<<<(NE + 255) / 256, 256, 0, s1>>>(edge_dst);                   // 2
    k_scan<<<1, 1024, 0, s1>>>();                                        // 3
    k_gru<<<2, G3, SMEM_GRU>>>(questions, Wh_f, bh_f, Wh_b, bh_b);      // 4 (ncu slot)
    k_perm<<<(NE + 255) / 256, 256, 0, s1>>>(edge_src, edge_dst, edge_type, w_comp); // 5
    cudaEventRecord(ev1, s1);
    k_qg<<<1, 256>>>(W_hg, b_hg);                                        // 6
    k_nf0<<<(NN * 32 + 255) / 256, 256>>>(node_descs, emb_desc);         // 7
    cudaStreamWaitEvent(0, ev1, 0);
    k_agg<<<(NN * 32 + 255) / 256, 256>>>();                             // 8
    k_rgcn<<<1250, 256>>>(bases, rgcn_bias);                             // 9
    k_sum<<<256, 256>>>();                                               // 10
    k_hidden<<<32, 128>>>(W1);                                           // 11
    k_logits<<<63, 256>>>(W2, b1, b2, out);                              // 12
}